// round 1
// baseline (speedup 1.0000x reference)
#include <cuda_runtime.h>
#include <math.h>

// Problem dims
#define MB  4
#define MS  2048
#define MD  1024
#define MNH 16
#define MHD 64
#define MM  (MB * MS)   // 8192 rows

// ---------------- scratch (allocation-free: __device__ globals) ----------------
__device__ float g_q[MM * MD];
__device__ float g_k[MM * MD];
__device__ float g_v[MM * MD];
__device__ float g_ctx[MM * MD];

// ---------------- GEMM: C = A[M,K] @ W[K,N] + bias -----------------------------
// 128x128 block tile, BK=8, 256 threads, 8x8 register tile per thread.
// blockIdx.z selects among up to 3 (W, bias, C) sets so QKV runs as one launch.
#define GBM 128
#define GBN 128
#define GBK 8

__global__ __launch_bounds__(256)
void gemm3_kernel(const float* __restrict__ A,
                  const float* __restrict__ W0, const float* __restrict__ W1,
                  const float* __restrict__ W2,
                  const float* __restrict__ b0, const float* __restrict__ b1,
                  const float* __restrict__ b2,
                  float* __restrict__ C0, float* __restrict__ C1,
                  float* __restrict__ C2,
                  int M, int N, int K)
{
    const float* W; const float* bias; float* C;
    if (blockIdx.z == 0)      { W = W0; bias = b0; C = C0; }
    else if (blockIdx.z == 1) { W = W1; bias = b1; C = C1; }
    else                      { W = W2; bias = b2; C = C2; }

    __shared__ float As[GBK][GBM];   // A tile stored transposed: As[k][m]
    __shared__ float Bs[GBK][GBN];

    const int tid  = threadIdx.x;
    const int row0 = blockIdx.y * GBM;
    const int col0 = blockIdx.x * GBN;

    // A tile load: 128 rows x 8 cols = 256 float4 (1 per thread)
    const int aRow = tid >> 1;            // 0..127
    const int aCol = (tid & 1) * 4;       // 0 or 4
    // B tile load: 8 rows x 128 cols = 256 float4 (1 per thread)
    const int bRow = tid >> 5;            // 0..7
    const int bCol = (tid & 31) * 4;      // 0..124

    const int tRow = (tid >> 4) * 8;      // 0..120
    const int tCol = (tid & 15) * 8;      // 0..120

    float acc[8][8];
    #pragma unroll
    for (int i = 0; i < 8; i++)
        #pragma unroll
        for (int j = 0; j < 8; j++) acc[i][j] = 0.f;

    const float* Aptr = A + (size_t)(row0 + aRow) * K + aCol;
    const float* Wptr = W + (size_t)bRow * N + col0 + bCol;

    for (int k0 = 0; k0 < K; k0 += GBK) {
        float4 a4 = *(const float4*)(Aptr + k0);
        As[aCol + 0][aRow] = a4.x;
        As[aCol + 1][aRow] = a4.y;
        As[aCol + 2][aRow] = a4.z;
        As[aCol + 3][aRow] = a4.w;
        float4 b4 = *(const float4*)(Wptr + (size_t)k0 * N);
        *(float4*)&Bs[bRow][bCol] = b4;
        __syncthreads();

        #pragma unroll
        for (int kk = 0; kk < GBK; kk++) {
            float ar[8], br[8];
            #pragma unroll
            for (int i = 0; i < 8; i++) ar[i] = As[kk][tRow + i];
            #pragma unroll
            for (int j = 0; j < 8; j++) br[j] = Bs[kk][tCol + j];
            #pragma unroll
            for (int i = 0; i < 8; i++)
                #pragma unroll
                for (int j = 0; j < 8; j++)
                    acc[i][j] += ar[i] * br[j];
        }
        __syncthreads();
    }

    float bv[8];
    #pragma unroll
    for (int j = 0; j < 8; j++) bv[j] = bias[col0 + tCol + j];

    #pragma unroll
    for (int i = 0; i < 8; i++) {
        float* crow = C + (size_t)(row0 + tRow + i) * N + col0 + tCol;
        float4 s0, s1;
        s0.x = acc[i][0] + bv[0]; s0.y = acc[i][1] + bv[1];
        s0.z = acc[i][2] + bv[2]; s0.w = acc[i][3] + bv[3];
        s1.x = acc[i][4] + bv[4]; s1.y = acc[i][5] + bv[5];
        s1.z = acc[i][6] + bv[6]; s1.w = acc[i][7] + bv[7];
        *(float4*)(crow + 0) = s0;
        *(float4*)(crow + 4) = s1;
    }
}

// ---------------- Flash attention: per (b,h), tiled online softmax --------------
// Block: 256 threads handles 64 q-rows; iterates 2048 k-rows in tiles of 32.
#define ABM 64
#define ABN 32

__global__ __launch_bounds__(256)
void attn_kernel(const float* __restrict__ mask, float* __restrict__ ctx)
{
    __shared__ float Qs[ABM][MHD + 1];
    __shared__ float Ks[ABN][MHD + 1];
    __shared__ float Vs[ABN][MHD + 1];
    __shared__ float Ss[ABM][ABN + 1];
    __shared__ float m_s[ABM], l_s[ABM], al_s[ABM];

    const int tid = threadIdx.x;
    const int bh  = blockIdx.y;
    const int b   = bh >> 4;   // / MNH
    const int h   = bh & 15;
    const int q0  = blockIdx.x * ABM;

    const size_t base = (size_t)b * MS * MD + (size_t)h * MHD;

    // Load Q tile (64 x 64 floats = 1024 float4)
    for (int i = tid; i < ABM * (MHD / 4); i += 256) {
        int r = i >> 4;
        int c = (i & 15) << 2;
        float4 t = *(const float4*)(g_q + base + (size_t)(q0 + r) * MD + c);
        Qs[r][c] = t.x; Qs[r][c + 1] = t.y; Qs[r][c + 2] = t.z; Qs[r][c + 3] = t.w;
    }
    if (tid < ABM) { m_s[tid] = -INFINITY; l_s[tid] = 0.f; }

    const int sy    = tid >> 4;   // 0..15 : owns S rows sy*4+r, O rows sy*4+r
    const int sx    = tid & 15;   // 0..15 : owns S cols sx*2+c, O cols sx*4+c
    const int srow  = tid >> 2;   // 0..63 : softmax row
    const int spart = tid & 3;    // 4 threads per softmax row

    float O[4][4];
    #pragma unroll
    for (int r = 0; r < 4; r++)
        #pragma unroll
        for (int c = 0; c < 4; c++) O[r][c] = 0.f;

    __syncthreads();

    const float scale = 0.125f;   // 1/sqrt(64)

    for (int kt = 0; kt < MS / ABN; kt++) {
        // Load K and V tiles (32 x 64 floats = 512 float4 each)
        for (int i = tid; i < ABN * (MHD / 4); i += 256) {
            int r = i >> 4;
            int c = (i & 15) << 2;
            size_t off = base + (size_t)(kt * ABN + r) * MD + c;
            float4 tk = *(const float4*)(g_k + off);
            Ks[r][c] = tk.x; Ks[r][c + 1] = tk.y; Ks[r][c + 2] = tk.z; Ks[r][c + 3] = tk.w;
            float4 tv = *(const float4*)(g_v + off);
            Vs[r][c] = tv.x; Vs[r][c + 1] = tv.y; Vs[r][c + 2] = tv.z; Vs[r][c + 3] = tv.w;
        }
        __syncthreads();

        // S = scale * Q K^T + mask  (64 x 32; thread computes 4x2)
        float sacc[4][2];
        #pragma unroll
        for (int r = 0; r < 4; r++) { sacc[r][0] = 0.f; sacc[r][1] = 0.f; }

        #pragma unroll 4
        for (int d = 0; d < MHD; d++) {
            float q0v = Qs[sy * 4 + 0][d];
            float q1v = Qs[sy * 4 + 1][d];
            float q2v = Qs[sy * 4 + 2][d];
            float q3v = Qs[sy * 4 + 3][d];
            float k0v = Ks[sx * 2 + 0][d];
            float k1v = Ks[sx * 2 + 1][d];
            sacc[0][0] += q0v * k0v;  sacc[0][1] += q0v * k1v;
            sacc[1][0] += q1v * k0v;  sacc[1][1] += q1v * k1v;
            sacc[2][0] += q2v * k0v;  sacc[2][1] += q2v * k1v;
            sacc[3][0] += q3v * k0v;  sacc[3][1] += q3v * k1v;
        }
        #pragma unroll
        for (int c = 0; c < 2; c++) {
            int kg = kt * ABN + sx * 2 + c;
            float mv = mask[b * MS + kg];
            #pragma unroll
            for (int r = 0; r < 4; r++)
                Ss[sy * 4 + r][sx * 2 + c] = sacc[r][c] * scale + mv;
        }
        __syncthreads();

        // Online softmax per row: 4 threads/row, 8 cols each
        float mloc = -INFINITY;
        #pragma unroll
        for (int i = 0; i < 8; i++) mloc = fmaxf(mloc, Ss[srow][spart * 8 + i]);
        mloc = fmaxf(mloc, __shfl_xor_sync(0xffffffffu, mloc, 1));
        mloc = fmaxf(mloc, __shfl_xor_sync(0xffffffffu, mloc, 2));
        float mold = m_s[srow];
        float mnew = fmaxf(mold, mloc);
        float lloc = 0.f;
        #pragma unroll
        for (int i = 0; i < 8; i++) {
            float p = __expf(Ss[srow][spart * 8 + i] - mnew);
            Ss[srow][spart * 8 + i] = p;
            lloc += p;
        }
        lloc += __shfl_xor_sync(0xffffffffu, lloc, 1);
        lloc += __shfl_xor_sync(0xffffffffu, lloc, 2);
        if (spart == 0) {
            float al = __expf(mold - mnew);
            m_s[srow]  = mnew;
            l_s[srow]  = l_s[srow] * al + lloc;
            al_s[srow] = al;
        }
        __syncthreads();

        // O = O * alpha + P @ V   (thread owns O[sy*4+r][sx*4+c])
        float alr[4];
        #pragma unroll
        for (int r = 0; r < 4; r++) alr[r] = al_s[sy * 4 + r];
        #pragma unroll
        for (int r = 0; r < 4; r++)
            #pragma unroll
            for (int c = 0; c < 4; c++) O[r][c] *= alr[r];

        #pragma unroll 4
        for (int j = 0; j < ABN; j++) {
            float s0 = Ss[sy * 4 + 0][j];
            float s1 = Ss[sy * 4 + 1][j];
            float s2 = Ss[sy * 4 + 2][j];
            float s3 = Ss[sy * 4 + 3][j];
            float v0 = Vs[j][sx * 4 + 0];
            float v1 = Vs[j][sx * 4 + 1];
            float v2 = Vs[j][sx * 4 + 2];
            float v3 = Vs[j][sx * 4 + 3];
            O[0][0] += s0 * v0; O[0][1] += s0 * v1; O[0][2] += s0 * v2; O[0][3] += s0 * v3;
            O[1][0] += s1 * v0; O[1][1] += s1 * v1; O[1][2] += s1 * v2; O[1][3] += s1 * v3;
            O[2][0] += s2 * v0; O[2][1] += s2 * v1; O[2][2] += s2 * v2; O[2][3] += s2 * v3;
            O[3][0] += s3 * v0; O[3][1] += s3 * v1; O[3][2] += s3 * v2; O[3][3] += s3 * v3;
        }
        __syncthreads();
    }

    // Normalize and write ctx in [B,S,D] layout (head h at cols h*64..h*64+63)
    #pragma unroll
    for (int r = 0; r < 4; r++) {
        float linv = 1.0f / l_s[sy * 4 + r];
        size_t off = base + (size_t)(q0 + sy * 4 + r) * MD + sx * 4;
        ctx[off + 0] = O[r][0] * linv;
        ctx[off + 1] = O[r][1] * linv;
        ctx[off + 2] = O[r][2] * linv;
        ctx[off + 3] = O[r][3] * linv;
    }
}

// ---------------- launch ----------------
extern "C" void kernel_launch(void* const* d_in, const int* in_sizes, int n_in,
                              void* d_out, int out_size)
{
    const float* x    = (const float*)d_in[0];
    const float* mask = (const float*)d_in[1];
    const float* Wq   = (const float*)d_in[2];
    const float* bq   = (const float*)d_in[3];
    const float* Wk   = (const float*)d_in[4];
    const float* bk   = (const float*)d_in[5];
    const float* Wv   = (const float*)d_in[6];
    const float* bv   = (const float*)d_in[7];
    const float* Wo   = (const float*)d_in[8];
    const float* bo   = (const float*)d_in[9];
    float* out = (float*)d_out;

    float *pq, *pk, *pv, *pctx;
    cudaGetSymbolAddress((void**)&pq,   g_q);
    cudaGetSymbolAddress((void**)&pk,   g_k);
    cudaGetSymbolAddress((void**)&pv,   g_v);
    cudaGetSymbolAddress((void**)&pctx, g_ctx);

    // 1) Fused QKV projections: q/k/v = x@W + b
    dim3 gqkv(MD / GBN, MM / GBM, 3);
    gemm3_kernel<<<gqkv, 256>>>(x, Wq, Wk, Wv, bq, bk, bv, pq, pk, pv,
                                MM, MD, MD);

    // 2) Flash attention -> ctx
    dim3 gattn(MS / ABM, MB * MNH);
    attn_kernel<<<gattn, 256>>>(mask, pctx);

    // 3) Output projection: out = ctx@Wo + bo
    dim3 go(MD / GBN, MM / GBM, 1);
    gemm3_kernel<<<go, 256>>>(pctx, Wo, Wo, Wo, bo, bo, bo, out, out, out,
                              MM, MD, MD);
}

// round 3
// speedup vs baseline: 1.3438x; 1.3438x over previous
#include <cuda_runtime.h>
#include <cuda_bf16.h>
#include <math.h>
#include <stdint.h>

// Problem dims
#define MB  4
#define MS  2048
#define MD  1024
#define MNH 16
#define MHD 64
#define MM  (MB * MS)   // 8192 rows

// ---------------- scratch (allocation-free: __device__ globals) ----------------
__device__ float g_q[MM * MD];
__device__ float g_k[MM * MD];
__device__ float g_v[MM * MD];
__device__ float g_ctx[MM * MD];
__device__ __nv_bfloat16 g_xhi[MM * MD];
__device__ __nv_bfloat16 g_xlo[MM * MD];
__device__ __nv_bfloat16 g_chi[MM * MD];
__device__ __nv_bfloat16 g_clo[MM * MD];
__device__ __nv_bfloat16 g_wthi[4 * MD * MD];   // W^T per matrix: [N,K] K-major
__device__ __nv_bfloat16 g_wtlo[4 * MD * MD];

// ======================= mma.sync helpers (sm_80+, no 'a'-gate) ===============
__device__ __forceinline__ uint32_t smem_to_u32(const void* p) {
    uint32_t a;
    asm("{ .reg .u64 t; cvta.to.shared.u64 t, %1; cvt.u32.u64 %0, t; }" : "=r"(a) : "l"(p));
    return a;
}

__device__ __forceinline__ void ldsm_x4(uint32_t* r, uint32_t addr) {
    asm volatile("ldmatrix.sync.aligned.m8n8.x4.shared.b16 {%0,%1,%2,%3}, [%4];"
                 : "=r"(r[0]), "=r"(r[1]), "=r"(r[2]), "=r"(r[3]) : "r"(addr));
}

__device__ __forceinline__ void mma_bf16(float* d, const uint32_t* a, const uint32_t* b) {
    asm volatile(
        "mma.sync.aligned.m16n8k16.row.col.f32.bf16.bf16.f32 "
        "{%0,%1,%2,%3}, {%4,%5,%6,%7}, {%8,%9}, {%0,%1,%2,%3};"
        : "+f"(d[0]), "+f"(d[1]), "+f"(d[2]), "+f"(d[3])
        : "r"(a[0]), "r"(a[1]), "r"(a[2]), "r"(a[3]), "r"(b[0]), "r"(b[1]));
}

// ======================= prep kernels =======================
__global__ __launch_bounds__(256)
void split_convert(const float* __restrict__ x,
                   __nv_bfloat16* __restrict__ hi, __nv_bfloat16* __restrict__ lo)
{
    int i = blockIdx.x * blockDim.x + threadIdx.x;  // float4 index
    float4 v = ((const float4*)x)[i];
    __nv_bfloat16 h0 = __float2bfloat16(v.x);
    __nv_bfloat16 h1 = __float2bfloat16(v.y);
    __nv_bfloat16 h2 = __float2bfloat16(v.z);
    __nv_bfloat16 h3 = __float2bfloat16(v.w);
    __nv_bfloat16 l0 = __float2bfloat16(v.x - __bfloat162float(h0));
    __nv_bfloat16 l1 = __float2bfloat16(v.y - __bfloat162float(h1));
    __nv_bfloat16 l2 = __float2bfloat16(v.z - __bfloat162float(h2));
    __nv_bfloat16 l3 = __float2bfloat16(v.w - __bfloat162float(h3));
    __nv_bfloat162* H = (__nv_bfloat162*)hi;
    __nv_bfloat162* L = (__nv_bfloat162*)lo;
    H[2*i]   = __nv_bfloat162(h0, h1);
    H[2*i+1] = __nv_bfloat162(h2, h3);
    L[2*i]   = __nv_bfloat162(l0, l1);
    L[2*i+1] = __nv_bfloat162(l2, l3);
}

__global__ __launch_bounds__(1024)
void transpose_split(const float* __restrict__ W0, const float* __restrict__ W1,
                     const float* __restrict__ W2, const float* __restrict__ W3,
                     __nv_bfloat16* __restrict__ hi, __nv_bfloat16* __restrict__ lo)
{
    __shared__ float t[32][33];
    int z = blockIdx.z;
    const float* src = (z == 0) ? W0 : (z == 1) ? W1 : (z == 2) ? W2 : W3;
    int k = blockIdx.y * 32 + threadIdx.y;
    int n = blockIdx.x * 32 + threadIdx.x;
    t[threadIdx.y][threadIdx.x] = src[k * MD + n];
    __syncthreads();
    int nn = blockIdx.x * 32 + threadIdx.y;
    int kk = blockIdx.y * 32 + threadIdx.x;
    float v = t[threadIdx.x][threadIdx.y];
    __nv_bfloat16 h = __float2bfloat16(v);
    __nv_bfloat16 l = __float2bfloat16(v - __bfloat162float(h));
    size_t o = (size_t)z * MD * MD + (size_t)nn * MD + kk;
    hi[o] = h;
    lo[o] = l;
}

// ======================= mma.sync GEMM =======================
// C[M,N] = A[M,K] @ W[K,N] + bias with 3-term bf16 split.
// A_hi/A_lo: [M,K] bf16 row-major. Bt_hi/Bt_lo: [N,K] bf16 row-major (W^T).
// CTA tile 128x128, BK=32, double-buffered. 8 warps: warp grid 4(m) x 2(n),
// warp tile 32x64 = 2 x 8 m16n8k16 fragments.
#define GBK 32
#define NCHK (MD / GBK)        // 32 chunks
#define SROW 40                // smem row stride in elems (32 + 8 pad)
#define BUF_E (128 * SROW)     // elems per buffer

// dynamic smem: [stage][4 buffers (Ah, Al, Bh, Bl)][128][SROW] bf16
#define STAGE_E (4 * BUF_E)
#define SMEM_TOTAL (2 * STAGE_E * 2)   // bytes

__global__ __launch_bounds__(256, 1)
void gemm_mma(const __nv_bfloat16* __restrict__ Ahi, const __nv_bfloat16* __restrict__ Alo,
              const __nv_bfloat16* __restrict__ Bthi, const __nv_bfloat16* __restrict__ Btlo,
              const float* __restrict__ b0, const float* __restrict__ b1,
              const float* __restrict__ b2,
              float* __restrict__ C0, float* __restrict__ C1, float* __restrict__ C2)
{
    extern __shared__ __nv_bfloat16 smem[];
    const int tid  = threadIdx.x;
    const int wid  = tid >> 5;
    const int lane = tid & 31;
    const int wm   = wid & 3;        // warp m index (0..3)
    const int wn   = wid >> 2;       // warp n index (0..1)

    const int z = blockIdx.z;
    const float* bias = (z == 0) ? b0 : (z == 1) ? b1 : b2;
    float* C = (z == 0) ? C0 : (z == 1) ? C1 : C2;
    const __nv_bfloat16* Bh = Bthi + (size_t)z * MD * MD;
    const __nv_bfloat16* Bl = Btlo + (size_t)z * MD * MD;

    const int n0 = blockIdx.x * 128;
    const int m0 = blockIdx.y * 128;

    __nv_bfloat16* sAh = smem;                   // [2][128][SROW], stage-major
    __nv_bfloat16* sAl = smem + 2 * BUF_E;
    __nv_bfloat16* sBh = smem + 4 * BUF_E;
    __nv_bfloat16* sBl = smem + 6 * BUF_E;

    // ---- global->smem mapping: 512 uint4 per buffer, 2 per thread ----
    // idx = tid + j*256 ; r = idx>>2 (0..127) ; c = (idx&3)*8 elems
    int r0g = (tid + 0)   >> 2, c0g = ((tid + 0)   & 3) << 3;
    int r1g = (tid + 256) >> 2, c1g = ((tid + 256) & 3) << 3;
    const size_t gA0 = (size_t)(m0 + r0g) * MD + c0g;
    const size_t gA1 = (size_t)(m0 + r1g) * MD + c1g;
    const size_t gB0 = (size_t)(n0 + r0g) * MD + c0g;
    const size_t gB1 = (size_t)(n0 + r1g) * MD + c1g;
    const int s0 = r0g * SROW + c0g;
    const int s1 = r1g * SROW + c1g;

    // ---- ldmatrix per-lane addresses (within a stage buffer) ----
    const uint32_t base_u32 = smem_to_u32(smem);
    // A frags: row = wm*32 + mf*16 + lane%16 ; col = (lane/16)*8 + ks*16
    const int a_r = wm * 32 + (lane & 15);
    const int a_c = (lane >> 4) << 3;
    // B frags: n-row = wn*64 + nf2*16 + ((lane>>4)<<3) + (lane&7) ; col = ((lane>>3)&1)*8 + ks*16
    const int b_r = wn * 64 + ((lane >> 4) << 3) + (lane & 7);
    const int b_c = ((lane >> 3) & 1) << 3;

    float acc[2][8][4];
    #pragma unroll
    for (int i = 0; i < 2; i++)
        #pragma unroll
        for (int j = 0; j < 8; j++)
            #pragma unroll
            for (int q = 0; q < 4; q++) acc[i][j][q] = 0.f;

    // ---- prologue: load chunk 0 into stage 0 ----
    {
        *(uint4*)(sAh + s0) = *(const uint4*)(Ahi + gA0);
        *(uint4*)(sAh + s1) = *(const uint4*)(Ahi + gA1);
        *(uint4*)(sAl + s0) = *(const uint4*)(Alo + gA0);
        *(uint4*)(sAl + s1) = *(const uint4*)(Alo + gA1);
        *(uint4*)(sBh + s0) = *(const uint4*)(Bh + gB0);
        *(uint4*)(sBh + s1) = *(const uint4*)(Bh + gB1);
        *(uint4*)(sBl + s0) = *(const uint4*)(Bl + gB0);
        *(uint4*)(sBl + s1) = *(const uint4*)(Bl + gB1);
    }
    __syncthreads();

    for (int ch = 0; ch < NCHK; ch++) {
        const int cur = ch & 1;
        const int nxt = cur ^ 1;

        // prefetch next chunk into registers
        uint4 pA0h, pA1h, pA0l, pA1l, pB0h, pB1h, pB0l, pB1l;
        if (ch < NCHK - 1) {
            const int kc = (ch + 1) * GBK;
            pA0h = *(const uint4*)(Ahi + gA0 + kc);
            pA1h = *(const uint4*)(Ahi + gA1 + kc);
            pA0l = *(const uint4*)(Alo + gA0 + kc);
            pA1l = *(const uint4*)(Alo + gA1 + kc);
            pB0h = *(const uint4*)(Bh + gB0 + kc);
            pB1h = *(const uint4*)(Bh + gB1 + kc);
            pB0l = *(const uint4*)(Bl + gB0 + kc);
            pB1l = *(const uint4*)(Bl + gB1 + kc);
        }

        // compute on stage cur: 2 k-steps of 16
        const uint32_t stA = base_u32 + (uint32_t)(cur * BUF_E) * 2;
        #pragma unroll
        for (int ks = 0; ks < 2; ks++) {
            uint32_t ah[2][4], al[2][4], bh[4][4], bl[4][4];
            const int kcol = ks * 16;
            #pragma unroll
            for (int mf = 0; mf < 2; mf++) {
                uint32_t off = (uint32_t)((a_r + mf * 16) * SROW + a_c + kcol) * 2;
                ldsm_x4(ah[mf], stA + 0 * (2 * BUF_E * 2) + off);
                ldsm_x4(al[mf], stA + 1 * (2 * BUF_E * 2) + off);
            }
            #pragma unroll
            for (int nf2 = 0; nf2 < 4; nf2++) {
                uint32_t off = (uint32_t)((b_r + nf2 * 16) * SROW + b_c + kcol) * 2;
                ldsm_x4(bh[nf2], stA + 2 * (2 * BUF_E * 2) + off);
                ldsm_x4(bl[nf2], stA + 3 * (2 * BUF_E * 2) + off);
            }
            #pragma unroll
            for (int mf = 0; mf < 2; mf++)
                #pragma unroll
                for (int nf = 0; nf < 8; nf++) {
                    const uint32_t* bhp = &bh[nf >> 1][(nf & 1) * 2];
                    const uint32_t* blp = &bl[nf >> 1][(nf & 1) * 2];
                    mma_bf16(acc[mf][nf], ah[mf], bhp);   // Ahi * Bhi
                    mma_bf16(acc[mf][nf], ah[mf], blp);   // Ahi * Blo
                    mma_bf16(acc[mf][nf], al[mf], bhp);   // Alo * Bhi
                }
        }

        // store prefetched regs into stage nxt
        if (ch < NCHK - 1) {
            __nv_bfloat16* dAh = sAh + nxt * BUF_E;
            __nv_bfloat16* dAl = sAl + nxt * BUF_E;
            __nv_bfloat16* dBh = sBh + nxt * BUF_E;
            __nv_bfloat16* dBl = sBl + nxt * BUF_E;
            *(uint4*)(dAh + s0) = pA0h;  *(uint4*)(dAh + s1) = pA1h;
            *(uint4*)(dAl + s0) = pA0l;  *(uint4*)(dAl + s1) = pA1l;
            *(uint4*)(dBh + s0) = pB0h;  *(uint4*)(dBh + s1) = pB1h;
            *(uint4*)(dBl + s0) = pB0l;  *(uint4*)(dBl + s1) = pB1l;
        }
        __syncthreads();
    }

    // ---- epilogue: add bias, store fp32 ----
    const int tq = lane >> 2;        // 0..7
    const int tr = lane & 3;         // 0..3
    #pragma unroll
    for (int mf = 0; mf < 2; mf++) {
        #pragma unroll
        for (int nf = 0; nf < 8; nf++) {
            const int n = n0 + wn * 64 + nf * 8 + tr * 2;
            const float bv0 = bias[n], bv1 = bias[n + 1];
            const int m_top = m0 + wm * 32 + mf * 16 + tq;
            float2 v0, v1;
            v0.x = acc[mf][nf][0] + bv0;  v0.y = acc[mf][nf][1] + bv1;
            v1.x = acc[mf][nf][2] + bv0;  v1.y = acc[mf][nf][3] + bv1;
            *(float2*)(C + (size_t)m_top * MD + n)       = v0;
            *(float2*)(C + (size_t)(m_top + 8) * MD + n) = v1;
        }
    }
}

// ---------------- Flash attention (unchanged, known-correct) --------------
#define ABM 64
#define ABN 32

__global__ __launch_bounds__(256)
void attn_kernel(const float* __restrict__ mask, float* __restrict__ ctx)
{
    __shared__ float Qs[ABM][MHD + 1];
    __shared__ float Ks[ABN][MHD + 1];
    __shared__ float Vs[ABN][MHD + 1];
    __shared__ float Ss[ABM][ABN + 1];
    __shared__ float m_s[ABM], l_s[ABM], al_s[ABM];

    const int tid = threadIdx.x;
    const int bh  = blockIdx.y;
    const int b   = bh >> 4;
    const int h   = bh & 15;
    const int q0  = blockIdx.x * ABM;

    const size_t base = (size_t)b * MS * MD + (size_t)h * MHD;

    for (int i = tid; i < ABM * (MHD / 4); i += 256) {
        int r = i >> 4;
        int c = (i & 15) << 2;
        float4 t = *(const float4*)(g_q + base + (size_t)(q0 + r) * MD + c);
        Qs[r][c] = t.x; Qs[r][c + 1] = t.y; Qs[r][c + 2] = t.z; Qs[r][c + 3] = t.w;
    }
    if (tid < ABM) { m_s[tid] = -INFINITY; l_s[tid] = 0.f; }

    const int sy    = tid >> 4;
    const int sx    = tid & 15;
    const int srow  = tid >> 2;
    const int spart = tid & 3;

    float O[4][4];
    #pragma unroll
    for (int r = 0; r < 4; r++)
        #pragma unroll
        for (int c = 0; c < 4; c++) O[r][c] = 0.f;

    __syncthreads();

    const float scale = 0.125f;

    for (int kt = 0; kt < MS / ABN; kt++) {
        for (int i = tid; i < ABN * (MHD / 4); i += 256) {
            int r = i >> 4;
            int c = (i & 15) << 2;
            size_t off = base + (size_t)(kt * ABN + r) * MD + c;
            float4 tk = *(const float4*)(g_k + off);
            Ks[r][c] = tk.x; Ks[r][c + 1] = tk.y; Ks[r][c + 2] = tk.z; Ks[r][c + 3] = tk.w;
            float4 tv = *(const float4*)(g_v + off);
            Vs[r][c] = tv.x; Vs[r][c + 1] = tv.y; Vs[r][c + 2] = tv.z; Vs[r][c + 3] = tv.w;
        }
        __syncthreads();

        float sacc[4][2];
        #pragma unroll
        for (int r = 0; r < 4; r++) { sacc[r][0] = 0.f; sacc[r][1] = 0.f; }

        #pragma unroll 4
        for (int d = 0; d < MHD; d++) {
            float q0v = Qs[sy * 4 + 0][d];
            float q1v = Qs[sy * 4 + 1][d];
            float q2v = Qs[sy * 4 + 2][d];
            float q3v = Qs[sy * 4 + 3][d];
            float k0v = Ks[sx * 2 + 0][d];
            float k1v = Ks[sx * 2 + 1][d];
            sacc[0][0] += q0v * k0v;  sacc[0][1] += q0v * k1v;
            sacc[1][0] += q1v * k0v;  sacc[1][1] += q1v * k1v;
            sacc[2][0] += q2v * k0v;  sacc[2][1] += q2v * k1v;
            sacc[3][0] += q3v * k0v;  sacc[3][1] += q3v * k1v;
        }
        #pragma unroll
        for (int c = 0; c < 2; c++) {
            int kg = kt * ABN + sx * 2 + c;
            float mv = mask[b * MS + kg];
            #pragma unroll
            for (int r = 0; r < 4; r++)
                Ss[sy * 4 + r][sx * 2 + c] = sacc[r][c] * scale + mv;
        }
        __syncthreads();

        float mloc = -INFINITY;
        #pragma unroll
        for (int i = 0; i < 8; i++) mloc = fmaxf(mloc, Ss[srow][spart * 8 + i]);
        mloc = fmaxf(mloc, __shfl_xor_sync(0xffffffffu, mloc, 1));
        mloc = fmaxf(mloc, __shfl_xor_sync(0xffffffffu, mloc, 2));
        float mold = m_s[srow];
        float mnew = fmaxf(mold, mloc);
        float lloc = 0.f;
        #pragma unroll
        for (int i = 0; i < 8; i++) {
            float p = __expf(Ss[srow][spart * 8 + i] - mnew);
            Ss[srow][spart * 8 + i] = p;
            lloc += p;
        }
        lloc += __shfl_xor_sync(0xffffffffu, lloc, 1);
        lloc += __shfl_xor_sync(0xffffffffu, lloc, 2);
        if (spart == 0) {
            float al = __expf(mold - mnew);
            m_s[srow]  = mnew;
            l_s[srow]  = l_s[srow] * al + lloc;
            al_s[srow] = al;
        }
        __syncthreads();

        float alr[4];
        #pragma unroll
        for (int r = 0; r < 4; r++) alr[r] = al_s[sy * 4 + r];
        #pragma unroll
        for (int r = 0; r < 4; r++)
            #pragma unroll
            for (int c = 0; c < 4; c++) O[r][c] *= alr[r];

        #pragma unroll 4
        for (int j = 0; j < ABN; j++) {
            float s0 = Ss[sy * 4 + 0][j];
            float s1 = Ss[sy * 4 + 1][j];
            float s2 = Ss[sy * 4 + 2][j];
            float s3 = Ss[sy * 4 + 3][j];
            float v0 = Vs[j][sx * 4 + 0];
            float v1 = Vs[j][sx * 4 + 1];
            float v2 = Vs[j][sx * 4 + 2];
            float v3 = Vs[j][sx * 4 + 3];
            O[0][0] += s0 * v0; O[0][1] += s0 * v1; O[0][2] += s0 * v2; O[0][3] += s0 * v3;
            O[1][0] += s1 * v0; O[1][1] += s1 * v1; O[1][2] += s1 * v2; O[1][3] += s1 * v3;
            O[2][0] += s2 * v0; O[2][1] += s2 * v1; O[2][2] += s2 * v2; O[2][3] += s2 * v3;
            O[3][0] += s3 * v0; O[3][1] += s3 * v1; O[3][2] += s3 * v2; O[3][3] += s3 * v3;
        }
        __syncthreads();
    }

    #pragma unroll
    for (int r = 0; r < 4; r++) {
        float linv = 1.0f / l_s[sy * 4 + r];
        size_t off = base + (size_t)(q0 + sy * 4 + r) * MD + sx * 4;
        ctx[off + 0] = O[r][0] * linv;
        ctx[off + 1] = O[r][1] * linv;
        ctx[off + 2] = O[r][2] * linv;
        ctx[off + 3] = O[r][3] * linv;
    }
}

// ---------------- launch ----------------
extern "C" void kernel_launch(void* const* d_in, const int* in_sizes, int n_in,
                              void* d_out, int out_size)
{
    const float* x    = (const float*)d_in[0];
    const float* mask = (const float*)d_in[1];
    const float* Wq   = (const float*)d_in[2];
    const float* bq   = (const float*)d_in[3];
    const float* Wk   = (const float*)d_in[4];
    const float* bk   = (const float*)d_in[5];
    const float* Wv   = (const float*)d_in[6];
    const float* bv   = (const float*)d_in[7];
    const float* Wo   = (const float*)d_in[8];
    const float* bo   = (const float*)d_in[9];
    float* out = (float*)d_out;

    float *pq, *pk, *pv, *pctx;
    __nv_bfloat16 *pxhi, *pxlo, *pchi, *pclo, *pwthi, *pwtlo;
    cudaGetSymbolAddress((void**)&pq,    g_q);
    cudaGetSymbolAddress((void**)&pk,    g_k);
    cudaGetSymbolAddress((void**)&pv,    g_v);
    cudaGetSymbolAddress((void**)&pctx,  g_ctx);
    cudaGetSymbolAddress((void**)&pxhi,  g_xhi);
    cudaGetSymbolAddress((void**)&pxlo,  g_xlo);
    cudaGetSymbolAddress((void**)&pchi,  g_chi);
    cudaGetSymbolAddress((void**)&pclo,  g_clo);
    cudaGetSymbolAddress((void**)&pwthi, g_wthi);
    cudaGetSymbolAddress((void**)&pwtlo, g_wtlo);

    cudaFuncSetAttribute(gemm_mma, cudaFuncAttributeMaxDynamicSharedMemorySize, SMEM_TOTAL);

    // 0) prep: split x; transpose+split all 4 weight matrices
    split_convert<<<(MM * MD / 4) / 256, 256>>>(x, pxhi, pxlo);
    dim3 gt(MD / 32, MD / 32, 4);
    transpose_split<<<gt, dim3(32, 32)>>>(Wq, Wk, Wv, Wo, pwthi, pwtlo);

    // 1) fused QKV projections via mma.sync bf16 (3-term split)
    dim3 gqkv(MD / 128, MM / 128, 3);
    gemm_mma<<<gqkv, 256, SMEM_TOTAL>>>(pxhi, pxlo, pwthi, pwtlo,
                                        bq, bk, bv, pq, pk, pv);

    // 2) flash attention -> ctx
    dim3 gattn(MS / ABM, MB * MNH);
    attn_kernel<<<gattn, 256>>>(mask, pctx);

    // 3) split ctx, then O projection -> out
    split_convert<<<(MM * MD / 4) / 256, 256>>>(pctx, pchi, pclo);
    dim3 go(MD / 128, MM / 128, 1);
    gemm_mma<<<go, 256, SMEM_TOTAL>>>(pchi, pclo, pwthi + 3 * (size_t)MD * MD,
                                      pwtlo + 3 * (size_t)MD * MD,
                                      bo, bo, bo, out, out, out);
}

// round 4
// speedup vs baseline: 2.5768x; 1.9176x over previous
#include <cuda_runtime.h>
#include <cuda_bf16.h>
#include <math.h>
#include <stdint.h>

// Problem dims
#define MB  4
#define MS  2048
#define MD  1024
#define MNH 16
#define MHD 64
#define MM  (MB * MS)   // 8192 rows

// ---------------- scratch (allocation-free: __device__ globals) ----------------
__device__ __nv_bfloat16 g_xhi[MM * MD];
__device__ __nv_bfloat16 g_xlo[MM * MD];
__device__ __nv_bfloat16 g_qhi[MM * MD];
__device__ __nv_bfloat16 g_qlo[MM * MD];
__device__ __nv_bfloat16 g_khi[MM * MD];
__device__ __nv_bfloat16 g_klo[MM * MD];
__device__ __nv_bfloat16 g_vhi[MM * MD];
__device__ __nv_bfloat16 g_vlo[MM * MD];
__device__ __nv_bfloat16 g_chi[MM * MD];
__device__ __nv_bfloat16 g_clo[MM * MD];
__device__ __nv_bfloat16 g_wthi[4 * MD * MD];   // W^T per matrix: [N,K] K-major
__device__ __nv_bfloat16 g_wtlo[4 * MD * MD];

// ======================= mma.sync helpers (sm_80+, no 'a'-gate) ===============
__device__ __forceinline__ uint32_t smem_to_u32(const void* p) {
    uint32_t a;
    asm("{ .reg .u64 t; cvta.to.shared.u64 t, %1; cvt.u32.u64 %0, t; }" : "=r"(a) : "l"(p));
    return a;
}

__device__ __forceinline__ void ldsm_x4(uint32_t* r, uint32_t addr) {
    asm volatile("ldmatrix.sync.aligned.m8n8.x4.shared.b16 {%0,%1,%2,%3}, [%4];"
                 : "=r"(r[0]), "=r"(r[1]), "=r"(r[2]), "=r"(r[3]) : "r"(addr));
}

__device__ __forceinline__ void mma_bf16(float* d, const uint32_t* a, const uint32_t* b) {
    asm volatile(
        "mma.sync.aligned.m16n8k16.row.col.f32.bf16.bf16.f32 "
        "{%0,%1,%2,%3}, {%4,%5,%6,%7}, {%8,%9}, {%0,%1,%2,%3};"
        : "+f"(d[0]), "+f"(d[1]), "+f"(d[2]), "+f"(d[3])
        : "r"(a[0]), "r"(a[1]), "r"(a[2]), "r"(a[3]), "r"(b[0]), "r"(b[1]));
}

__device__ __forceinline__ uint32_t pack_bf2(float a, float b) {
    __nv_bfloat162 t = __floats2bfloat162_rn(a, b);
    return *(uint32_t*)&t;
}
__device__ __forceinline__ void split2(float a, float b, uint32_t& hi, uint32_t& lo) {
    __nv_bfloat16 ha = __float2bfloat16(a);
    __nv_bfloat16 hb = __float2bfloat16(b);
    __nv_bfloat162 h2(ha, hb);
    hi = *(uint32_t*)&h2;
    lo = pack_bf2(a - __bfloat162float(ha), b - __bfloat162float(hb));
}

// ======================= prep kernels =======================
__global__ __launch_bounds__(256)
void split_convert(const float* __restrict__ x,
                   __nv_bfloat16* __restrict__ hi, __nv_bfloat16* __restrict__ lo)
{
    int i = blockIdx.x * blockDim.x + threadIdx.x;  // float4 index
    float4 v = ((const float4*)x)[i];
    uint32_t h01, l01, h23, l23;
    split2(v.x, v.y, h01, l01);
    split2(v.z, v.w, h23, l23);
    uint32_t* H = (uint32_t*)hi;
    uint32_t* L = (uint32_t*)lo;
    H[2*i] = h01;  H[2*i+1] = h23;
    L[2*i] = l01;  L[2*i+1] = l23;
}

__global__ __launch_bounds__(1024)
void transpose_split(const float* __restrict__ W0, const float* __restrict__ W1,
                     const float* __restrict__ W2, const float* __restrict__ W3,
                     __nv_bfloat16* __restrict__ hi, __nv_bfloat16* __restrict__ lo)
{
    __shared__ float t[32][33];
    int z = blockIdx.z;
    const float* src = (z == 0) ? W0 : (z == 1) ? W1 : (z == 2) ? W2 : W3;
    int k = blockIdx.y * 32 + threadIdx.y;
    int n = blockIdx.x * 32 + threadIdx.x;
    t[threadIdx.y][threadIdx.x] = src[k * MD + n];
    __syncthreads();
    int nn = blockIdx.x * 32 + threadIdx.y;
    int kk = blockIdx.y * 32 + threadIdx.x;
    float v = t[threadIdx.x][threadIdx.y];
    __nv_bfloat16 h = __float2bfloat16(v);
    __nv_bfloat16 l = __float2bfloat16(v - __bfloat162float(h));
    size_t o = (size_t)z * MD * MD + (size_t)nn * MD + kk;
    hi[o] = h;
    lo[o] = l;
}

// ======================= mma.sync GEMM =======================
// C = A @ W + bias, 3-term bf16 split. Optionally writes bf16 hi/lo split
// output (for QKV) instead of fp32.
#define GBK 32
#define NCHK (MD / GBK)
#define SROW 40
#define BUF_E (128 * SROW)
#define SMEM_TOTAL (8 * BUF_E * 2)

__global__ __launch_bounds__(256, 1)
void gemm_mma(const __nv_bfloat16* __restrict__ Ahi, const __nv_bfloat16* __restrict__ Alo,
              const __nv_bfloat16* __restrict__ Bthi, const __nv_bfloat16* __restrict__ Btlo,
              const float* __restrict__ b0, const float* __restrict__ b1,
              const float* __restrict__ b2,
              float* __restrict__ Cf,
              __nv_bfloat16* __restrict__ H0, __nv_bfloat16* __restrict__ H1,
              __nv_bfloat16* __restrict__ H2,
              __nv_bfloat16* __restrict__ L0, __nv_bfloat16* __restrict__ L1,
              __nv_bfloat16* __restrict__ L2)
{
    extern __shared__ __nv_bfloat16 smem[];
    const int tid  = threadIdx.x;
    const int wid  = tid >> 5;
    const int lane = tid & 31;
    const int wm   = wid & 3;
    const int wn   = wid >> 2;

    const int z = blockIdx.z;
    const float* bias = (z == 0) ? b0 : (z == 1) ? b1 : b2;
    __nv_bfloat16* Hout = (z == 0) ? H0 : (z == 1) ? H1 : H2;
    __nv_bfloat16* Lout = (z == 0) ? L0 : (z == 1) ? L1 : L2;
    const __nv_bfloat16* Bh = Bthi + (size_t)z * MD * MD;
    const __nv_bfloat16* Bl = Btlo + (size_t)z * MD * MD;

    const int n0 = blockIdx.x * 128;
    const int m0 = blockIdx.y * 128;

    __nv_bfloat16* sAh = smem;
    __nv_bfloat16* sAl = smem + 2 * BUF_E;
    __nv_bfloat16* sBh = smem + 4 * BUF_E;
    __nv_bfloat16* sBl = smem + 6 * BUF_E;

    int r0g = (tid + 0)   >> 2, c0g = ((tid + 0)   & 3) << 3;
    int r1g = (tid + 256) >> 2, c1g = ((tid + 256) & 3) << 3;
    const size_t gA0 = (size_t)(m0 + r0g) * MD + c0g;
    const size_t gA1 = (size_t)(m0 + r1g) * MD + c1g;
    const size_t gB0 = (size_t)(n0 + r0g) * MD + c0g;
    const size_t gB1 = (size_t)(n0 + r1g) * MD + c1g;
    const int s0 = r0g * SROW + c0g;
    const int s1 = r1g * SROW + c1g;

    const uint32_t base_u32 = smem_to_u32(smem);
    const int a_r = wm * 32 + (lane & 15);
    const int a_c = (lane >> 4) << 3;
    const int b_r = wn * 64 + ((lane >> 4) << 3) + (lane & 7);
    const int b_c = ((lane >> 3) & 1) << 3;

    float acc[2][8][4];
    #pragma unroll
    for (int i = 0; i < 2; i++)
        #pragma unroll
        for (int j = 0; j < 8; j++)
            #pragma unroll
            for (int q = 0; q < 4; q++) acc[i][j][q] = 0.f;

    {
        *(uint4*)(sAh + s0) = *(const uint4*)(Ahi + gA0);
        *(uint4*)(sAh + s1) = *(const uint4*)(Ahi + gA1);
        *(uint4*)(sAl + s0) = *(const uint4*)(Alo + gA0);
        *(uint4*)(sAl + s1) = *(const uint4*)(Alo + gA1);
        *(uint4*)(sBh + s0) = *(const uint4*)(Bh + gB0);
        *(uint4*)(sBh + s1) = *(const uint4*)(Bh + gB1);
        *(uint4*)(sBl + s0) = *(const uint4*)(Bl + gB0);
        *(uint4*)(sBl + s1) = *(const uint4*)(Bl + gB1);
    }
    __syncthreads();

    for (int ch = 0; ch < NCHK; ch++) {
        const int cur = ch & 1;
        const int nxt = cur ^ 1;

        uint4 pA0h, pA1h, pA0l, pA1l, pB0h, pB1h, pB0l, pB1l;
        if (ch < NCHK - 1) {
            const int kc = (ch + 1) * GBK;
            pA0h = *(const uint4*)(Ahi + gA0 + kc);
            pA1h = *(const uint4*)(Ahi + gA1 + kc);
            pA0l = *(const uint4*)(Alo + gA0 + kc);
            pA1l = *(const uint4*)(Alo + gA1 + kc);
            pB0h = *(const uint4*)(Bh + gB0 + kc);
            pB1h = *(const uint4*)(Bh + gB1 + kc);
            pB0l = *(const uint4*)(Bl + gB0 + kc);
            pB1l = *(const uint4*)(Bl + gB1 + kc);
        }

        const uint32_t stA = base_u32 + (uint32_t)(cur * BUF_E) * 2;
        #pragma unroll
        for (int ks = 0; ks < 2; ks++) {
            uint32_t ah[2][4], al[2][4], bh[4][4], bl[4][4];
            const int kcol = ks * 16;
            #pragma unroll
            for (int mf = 0; mf < 2; mf++) {
                uint32_t off = (uint32_t)((a_r + mf * 16) * SROW + a_c + kcol) * 2;
                ldsm_x4(ah[mf], stA + 0 * (2 * BUF_E * 2) + off);
                ldsm_x4(al[mf], stA + 1 * (2 * BUF_E * 2) + off);
            }
            #pragma unroll
            for (int nf2 = 0; nf2 < 4; nf2++) {
                uint32_t off = (uint32_t)((b_r + nf2 * 16) * SROW + b_c + kcol) * 2;
                ldsm_x4(bh[nf2], stA + 2 * (2 * BUF_E * 2) + off);
                ldsm_x4(bl[nf2], stA + 3 * (2 * BUF_E * 2) + off);
            }
            #pragma unroll
            for (int mf = 0; mf < 2; mf++)
                #pragma unroll
                for (int nf = 0; nf < 8; nf++) {
                    const uint32_t* bhp = &bh[nf >> 1][(nf & 1) * 2];
                    const uint32_t* blp = &bl[nf >> 1][(nf & 1) * 2];
                    mma_bf16(acc[mf][nf], ah[mf], bhp);
                    mma_bf16(acc[mf][nf], ah[mf], blp);
                    mma_bf16(acc[mf][nf], al[mf], bhp);
                }
        }

        if (ch < NCHK - 1) {
            __nv_bfloat16* dAh = sAh + nxt * BUF_E;
            __nv_bfloat16* dAl = sAl + nxt * BUF_E;
            __nv_bfloat16* dBh = sBh + nxt * BUF_E;
            __nv_bfloat16* dBl = sBl + nxt * BUF_E;
            *(uint4*)(dAh + s0) = pA0h;  *(uint4*)(dAh + s1) = pA1h;
            *(uint4*)(dAl + s0) = pA0l;  *(uint4*)(dAl + s1) = pA1l;
            *(uint4*)(dBh + s0) = pB0h;  *(uint4*)(dBh + s1) = pB1h;
            *(uint4*)(dBl + s0) = pB0l;  *(uint4*)(dBl + s1) = pB1l;
        }
        __syncthreads();
    }

    const int tq = lane >> 2;
    const int tr = lane & 3;
    #pragma unroll
    for (int mf = 0; mf < 2; mf++) {
        #pragma unroll
        for (int nf = 0; nf < 8; nf++) {
            const int n = n0 + wn * 64 + nf * 8 + tr * 2;
            const float bv0 = bias[n], bv1 = bias[n + 1];
            const int m_top = m0 + wm * 32 + mf * 16 + tq;
            float v0 = acc[mf][nf][0] + bv0, v1 = acc[mf][nf][1] + bv1;
            float v2 = acc[mf][nf][2] + bv0, v3 = acc[mf][nf][3] + bv1;
            if (Hout) {
                uint32_t h01, l01, h23, l23;
                split2(v0, v1, h01, l01);
                split2(v2, v3, h23, l23);
                *(uint32_t*)(Hout + (size_t)m_top * MD + n)       = h01;
                *(uint32_t*)(Lout + (size_t)m_top * MD + n)       = l01;
                *(uint32_t*)(Hout + (size_t)(m_top + 8) * MD + n) = h23;
                *(uint32_t*)(Lout + (size_t)(m_top + 8) * MD + n) = l23;
            } else {
                float2 w0, w1;
                w0.x = v0; w0.y = v1;
                w1.x = v2; w1.y = v3;
                *(float2*)(Cf + (size_t)m_top * MD + n)       = w0;
                *(float2*)(Cf + (size_t)(m_top + 8) * MD + n) = w1;
            }
        }
    }
}

// ======================= flash attention on mma.sync =======================
// CTA: 128 q-rows x one (b,h). 8 warps, each owns 16 q-rows.
// kv tiles of 64, 3-term split for QK^T and PV, fp32 online softmax.
#define SR2 72                    // 64 + 8 pad (elems)
#define KBUF (64 * SR2)           // 4608 elems per 64x72 buffer

__global__ __launch_bounds__(256, 1)
void attn_mma(const float* __restrict__ mask,
              __nv_bfloat16* __restrict__ chi, __nv_bfloat16* __restrict__ clo)
{
    // overlay: Q(hi,lo) 128x72 each  <->  K(hi,lo) + Vt(hi,lo) 64x72 each
    __shared__ __nv_bfloat16 sm[4 * KBUF];
    __shared__ float ms[64];

    const int tid  = threadIdx.x;
    const int wid  = tid >> 5;
    const int lane = tid & 31;
    const int bh   = blockIdx.y;
    const int b    = bh >> 4;
    const int h    = bh & 15;
    const int q0   = blockIdx.x * 128;

    const uint32_t sbase = smem_to_u32(sm);

    // ---- load Q tile (128x64 hi/lo) into overlay, frag it ----
    #pragma unroll
    for (int it = 0; it < 4; it++) {
        int i = tid + it * 256;
        int r = i >> 3, c = (i & 7) << 3;
        size_t g = (size_t)(b * MS + q0 + r) * MD + h * 64 + c;
        *(uint4*)&sm[r * SR2 + c]            = *(const uint4*)(g_qhi + g);
        *(uint4*)&sm[2 * KBUF + r * SR2 + c] = *(const uint4*)(g_qlo + g);
    }
    __syncthreads();

    uint32_t qh[4][4], ql[4][4];
    {
        const int a_r = wid * 16 + (lane & 15);
        const int a_c = (lane >> 4) << 3;
        #pragma unroll
        for (int kf = 0; kf < 4; kf++) {
            uint32_t off = (uint32_t)(a_r * SR2 + a_c + kf * 16) * 2;
            ldsm_x4(qh[kf], sbase + off);
            ldsm_x4(ql[kf], sbase + 2 * KBUF * 2 + off);
        }
    }

    const int b_r = ((lane >> 4) << 3) + (lane & 7);
    const int b_c = ((lane >> 3) & 1) << 3;
    const int cq  = (lane & 3) * 2;

    float m0 = -INFINITY, m1 = -INFINITY, l0 = 0.f, l1 = 0.f;
    float o[8][4];
    #pragma unroll
    for (int nf = 0; nf < 8; nf++)
        #pragma unroll
        for (int q = 0; q < 4; q++) o[nf][q] = 0.f;

    for (int kt = 0; kt < MS / 64; kt++) {
        __syncthreads();   // previous tile fully consumed
        // ---- fill K (straight) and Vt (transposed) hi/lo + mask ----
        #pragma unroll
        for (int it = 0; it < 2; it++) {
            int i = tid + it * 256;
            int r = i >> 3, c = (i & 7) << 3;
            size_t g = (size_t)(b * MS + kt * 64 + r) * MD + h * 64 + c;
            *(uint4*)&sm[0 * KBUF + r * SR2 + c] = *(const uint4*)(g_khi + g);
            *(uint4*)&sm[1 * KBUF + r * SR2 + c] = *(const uint4*)(g_klo + g);
            __nv_bfloat16 tmp[8];
            *(uint4*)tmp = *(const uint4*)(g_vhi + g);
            #pragma unroll
            for (int j = 0; j < 8; j++) sm[2 * KBUF + (c + j) * SR2 + r] = tmp[j];
            *(uint4*)tmp = *(const uint4*)(g_vlo + g);
            #pragma unroll
            for (int j = 0; j < 8; j++) sm[3 * KBUF + (c + j) * SR2 + r] = tmp[j];
        }
        if (tid < 64) ms[tid] = mask[b * MS + kt * 64 + tid];
        __syncthreads();

        // ---- S = Q K^T (3-term) ----
        float s[8][4];
        #pragma unroll
        for (int nf = 0; nf < 8; nf++)
            #pragma unroll
            for (int q = 0; q < 4; q++) s[nf][q] = 0.f;

        #pragma unroll
        for (int ks = 0; ks < 4; ks++) {
            uint32_t kh[4][4], kl[4][4];
            #pragma unroll
            for (int nf2 = 0; nf2 < 4; nf2++) {
                uint32_t off = (uint32_t)((b_r + nf2 * 16) * SR2 + b_c + ks * 16) * 2;
                ldsm_x4(kh[nf2], sbase + 0 * KBUF * 2 + off);
                ldsm_x4(kl[nf2], sbase + 1 * KBUF * 2 + off);
            }
            #pragma unroll
            for (int nf = 0; nf < 8; nf++) {
                const uint32_t* bhp = &kh[nf >> 1][(nf & 1) * 2];
                const uint32_t* blp = &kl[nf >> 1][(nf & 1) * 2];
                mma_bf16(s[nf], qh[ks], bhp);
                mma_bf16(s[nf], qh[ks], blp);
                mma_bf16(s[nf], ql[ks], bhp);
            }
        }

        // ---- scale + mask ----
        #pragma unroll
        for (int nf = 0; nf < 8; nf++) {
            float ma = ms[nf * 8 + cq], mb = ms[nf * 8 + cq + 1];
            s[nf][0] = s[nf][0] * 0.125f + ma;
            s[nf][1] = s[nf][1] * 0.125f + mb;
            s[nf][2] = s[nf][2] * 0.125f + ma;
            s[nf][3] = s[nf][3] * 0.125f + mb;
        }

        // ---- online softmax (rows r0 = lane/4, r1 = r0+8) ----
        float rm0 = -INFINITY, rm1 = -INFINITY;
        #pragma unroll
        for (int nf = 0; nf < 8; nf++) {
            rm0 = fmaxf(rm0, fmaxf(s[nf][0], s[nf][1]));
            rm1 = fmaxf(rm1, fmaxf(s[nf][2], s[nf][3]));
        }
        rm0 = fmaxf(rm0, __shfl_xor_sync(0xffffffffu, rm0, 1));
        rm0 = fmaxf(rm0, __shfl_xor_sync(0xffffffffu, rm0, 2));
        rm1 = fmaxf(rm1, __shfl_xor_sync(0xffffffffu, rm1, 1));
        rm1 = fmaxf(rm1, __shfl_xor_sync(0xffffffffu, rm1, 2));
        float nm0 = fmaxf(m0, rm0), nm1 = fmaxf(m1, rm1);
        float al0 = __expf(m0 - nm0), al1 = __expf(m1 - nm1);
        m0 = nm0;  m1 = nm1;

        float ls0 = 0.f, ls1 = 0.f;
        #pragma unroll
        for (int nf = 0; nf < 8; nf++) {
            s[nf][0] = __expf(s[nf][0] - nm0);
            s[nf][1] = __expf(s[nf][1] - nm0);
            s[nf][2] = __expf(s[nf][2] - nm1);
            s[nf][3] = __expf(s[nf][3] - nm1);
            ls0 += s[nf][0] + s[nf][1];
            ls1 += s[nf][2] + s[nf][3];
        }
        ls0 += __shfl_xor_sync(0xffffffffu, ls0, 1);
        ls0 += __shfl_xor_sync(0xffffffffu, ls0, 2);
        ls1 += __shfl_xor_sync(0xffffffffu, ls1, 1);
        ls1 += __shfl_xor_sync(0xffffffffu, ls1, 2);
        l0 = l0 * al0 + ls0;
        l1 = l1 * al1 + ls1;

        #pragma unroll
        for (int nf = 0; nf < 8; nf++) {
            o[nf][0] *= al0;  o[nf][1] *= al0;
            o[nf][2] *= al1;  o[nf][3] *= al1;
        }

        // ---- repack P (accumulator layout -> A-fragment layout), hi/lo ----
        uint32_t ph[4][4], pl[4][4];
        #pragma unroll
        for (int kf = 0; kf < 4; kf++) {
            split2(s[2*kf][0],   s[2*kf][1],   ph[kf][0], pl[kf][0]);
            split2(s[2*kf][2],   s[2*kf][3],   ph[kf][1], pl[kf][1]);
            split2(s[2*kf+1][0], s[2*kf+1][1], ph[kf][2], pl[kf][2]);
            split2(s[2*kf+1][2], s[2*kf+1][3], ph[kf][3], pl[kf][3]);
        }

        // ---- O += P V (3-term) ----
        #pragma unroll
        for (int ks = 0; ks < 4; ks++) {
            uint32_t vh[4][4], vl[4][4];
            #pragma unroll
            for (int nf2 = 0; nf2 < 4; nf2++) {
                uint32_t off = (uint32_t)((b_r + nf2 * 16) * SR2 + b_c + ks * 16) * 2;
                ldsm_x4(vh[nf2], sbase + 2 * KBUF * 2 + off);
                ldsm_x4(vl[nf2], sbase + 3 * KBUF * 2 + off);
            }
            #pragma unroll
            for (int nf = 0; nf < 8; nf++) {
                const uint32_t* bhp = &vh[nf >> 1][(nf & 1) * 2];
                const uint32_t* blp = &vl[nf >> 1][(nf & 1) * 2];
                mma_bf16(o[nf], ph[ks], bhp);
                mma_bf16(o[nf], ph[ks], blp);
                mma_bf16(o[nf], pl[ks], bhp);
            }
        }
    }

    // ---- finalize: O /= l, write ctx hi/lo bf16 ----
    float i0 = 1.f / l0, i1 = 1.f / l1;
    const int r0 = lane >> 2;
    const size_t mrow = (size_t)(b * MS + q0 + wid * 16 + r0);
    #pragma unroll
    for (int nf = 0; nf < 8; nf++) {
        int d = h * 64 + nf * 8 + cq;
        float v0 = o[nf][0] * i0, v1 = o[nf][1] * i0;
        float v2 = o[nf][2] * i1, v3 = o[nf][3] * i1;
        uint32_t h01, l01, h23, l23;
        split2(v0, v1, h01, l01);
        split2(v2, v3, h23, l23);
        *(uint32_t*)(chi + mrow * MD + d)       = h01;
        *(uint32_t*)(clo + mrow * MD + d)       = l01;
        *(uint32_t*)(chi + (mrow + 8) * MD + d) = h23;
        *(uint32_t*)(clo + (mrow + 8) * MD + d) = l23;
    }
}

// ---------------- launch ----------------
extern "C" void kernel_launch(void* const* d_in, const int* in_sizes, int n_in,
                              void* d_out, int out_size)
{
    const float* x    = (const float*)d_in[0];
    const float* mask = (const float*)d_in[1];
    const float* Wq   = (const float*)d_in[2];
    const float* bq   = (const float*)d_in[3];
    const float* Wk   = (const float*)d_in[4];
    const float* bk   = (const float*)d_in[5];
    const float* Wv   = (const float*)d_in[6];
    const float* bv   = (const float*)d_in[7];
    const float* Wo   = (const float*)d_in[8];
    const float* bo   = (const float*)d_in[9];
    float* out = (float*)d_out;

    __nv_bfloat16 *pxhi, *pxlo, *pqhi, *pqlo, *pkhi, *pklo, *pvhi, *pvlo;
    __nv_bfloat16 *pchi, *pclo, *pwthi, *pwtlo;
    cudaGetSymbolAddress((void**)&pxhi,  g_xhi);
    cudaGetSymbolAddress((void**)&pxlo,  g_xlo);
    cudaGetSymbolAddress((void**)&pqhi,  g_qhi);
    cudaGetSymbolAddress((void**)&pqlo,  g_qlo);
    cudaGetSymbolAddress((void**)&pkhi,  g_khi);
    cudaGetSymbolAddress((void**)&pklo,  g_klo);
    cudaGetSymbolAddress((void**)&pvhi,  g_vhi);
    cudaGetSymbolAddress((void**)&pvlo,  g_vlo);
    cudaGetSymbolAddress((void**)&pchi,  g_chi);
    cudaGetSymbolAddress((void**)&pclo,  g_clo);
    cudaGetSymbolAddress((void**)&pwthi, g_wthi);
    cudaGetSymbolAddress((void**)&pwtlo, g_wtlo);

    cudaFuncSetAttribute(gemm_mma, cudaFuncAttributeMaxDynamicSharedMemorySize, SMEM_TOTAL);

    // 0) prep
    split_convert<<<(MM * MD / 4) / 256, 256>>>(x, pxhi, pxlo);
    dim3 gt(MD / 32, MD / 32, 4);
    transpose_split<<<gt, dim3(32, 32)>>>(Wq, Wk, Wv, Wo, pwthi, pwtlo);

    // 1) fused QKV projections -> bf16 hi/lo outputs
    dim3 gqkv(MD / 128, MM / 128, 3);
    gemm_mma<<<gqkv, 256, SMEM_TOTAL>>>(pxhi, pxlo, pwthi, pwtlo,
                                        bq, bk, bv, nullptr,
                                        pqhi, pkhi, pvhi, pqlo, pklo, pvlo);

    // 2) flash attention (tensor cores) -> ctx hi/lo
    dim3 gattn(MS / 128, MB * MNH);
    attn_mma<<<gattn, 256>>>(mask, pchi, pclo);

    // 3) O projection -> fp32 out
    dim3 go(MD / 128, MM / 128, 1);
    gemm_mma<<<go, 256, SMEM_TOTAL>>>(pchi, pclo, pwthi + 3 * (size_t)MD * MD,
                                      pwtlo + 3 * (size_t)MD * MD,
                                      bo, bo, bo, out,
                                      nullptr, nullptr, nullptr,
                                      nullptr, nullptr, nullptr);
}

// round 5
// speedup vs baseline: 3.3015x; 1.2812x over previous
#include <cuda_runtime.h>
#include <cuda_bf16.h>
#include <math.h>
#include <stdint.h>

// Problem dims
#define MB  4
#define MS  2048
#define MD  1024
#define MNH 16
#define MHD 64
#define MM  (MB * MS)   // 8192 rows

// ---------------- scratch (allocation-free: __device__ globals) ----------------
__device__ __nv_bfloat16 g_xhi[MM * MD];
__device__ __nv_bfloat16 g_xlo[MM * MD];
__device__ __nv_bfloat16 g_qhi[MM * MD];
__device__ __nv_bfloat16 g_qlo[MM * MD];
__device__ __nv_bfloat16 g_khi[MM * MD];
__device__ __nv_bfloat16 g_klo[MM * MD];
__device__ __nv_bfloat16 g_vhi[MM * MD];
__device__ __nv_bfloat16 g_vlo[MM * MD];
__device__ __nv_bfloat16 g_chi[MM * MD];
__device__ __nv_bfloat16 g_clo[MM * MD];
__device__ __nv_bfloat16 g_wthi[4 * MD * MD];   // W^T per matrix: [N,K] K-major
__device__ __nv_bfloat16 g_wtlo[4 * MD * MD];

// ======================= mma.sync helpers (sm_80+, no 'a'-gate) ===============
__device__ __forceinline__ uint32_t smem_to_u32(const void* p) {
    uint32_t a;
    asm("{ .reg .u64 t; cvta.to.shared.u64 t, %1; cvt.u32.u64 %0, t; }" : "=r"(a) : "l"(p));
    return a;
}

__device__ __forceinline__ void ldsm_x4(uint32_t* r, uint32_t addr) {
    asm volatile("ldmatrix.sync.aligned.m8n8.x4.shared.b16 {%0,%1,%2,%3}, [%4];"
                 : "=r"(r[0]), "=r"(r[1]), "=r"(r[2]), "=r"(r[3]) : "r"(addr));
}
__device__ __forceinline__ void ldsm_x4_t(uint32_t* r, uint32_t addr) {
    asm volatile("ldmatrix.sync.aligned.m8n8.x4.trans.shared.b16 {%0,%1,%2,%3}, [%4];"
                 : "=r"(r[0]), "=r"(r[1]), "=r"(r[2]), "=r"(r[3]) : "r"(addr));
}

__device__ __forceinline__ void mma_bf16(float* d, const uint32_t* a, const uint32_t* b) {
    asm volatile(
        "mma.sync.aligned.m16n8k16.row.col.f32.bf16.bf16.f32 "
        "{%0,%1,%2,%3}, {%4,%5,%6,%7}, {%8,%9}, {%0,%1,%2,%3};"
        : "+f"(d[0]), "+f"(d[1]), "+f"(d[2]), "+f"(d[3])
        : "r"(a[0]), "r"(a[1]), "r"(a[2]), "r"(a[3]), "r"(b[0]), "r"(b[1]));
}

#define CP_ASYNC16(dst, src) \
    asm volatile("cp.async.cg.shared.global [%0], [%1], 16;" :: "r"(dst), "l"(src))
#define CP_COMMIT() asm volatile("cp.async.commit_group;")
#define CP_WAIT0()  asm volatile("cp.async.wait_group 0;")

__device__ __forceinline__ uint32_t pack_bf2(float a, float b) {
    __nv_bfloat162 t = __floats2bfloat162_rn(a, b);
    return *(uint32_t*)&t;
}
__device__ __forceinline__ void split2(float a, float b, uint32_t& hi, uint32_t& lo) {
    __nv_bfloat16 ha = __float2bfloat16(a);
    __nv_bfloat16 hb = __float2bfloat16(b);
    __nv_bfloat162 h2(ha, hb);
    hi = *(uint32_t*)&h2;
    lo = pack_bf2(a - __bfloat162float(ha), b - __bfloat162float(hb));
}

// ======================= prep kernels =======================
__global__ __launch_bounds__(256)
void split_convert(const float* __restrict__ x,
                   __nv_bfloat16* __restrict__ hi, __nv_bfloat16* __restrict__ lo)
{
    int i = blockIdx.x * blockDim.x + threadIdx.x;  // float4 index
    float4 v = ((const float4*)x)[i];
    uint32_t h01, l01, h23, l23;
    split2(v.x, v.y, h01, l01);
    split2(v.z, v.w, h23, l23);
    uint32_t* H = (uint32_t*)hi;
    uint32_t* L = (uint32_t*)lo;
    H[2*i] = h01;  H[2*i+1] = h23;
    L[2*i] = l01;  L[2*i+1] = l23;
}

__global__ __launch_bounds__(1024)
void transpose_split(const float* __restrict__ W0, const float* __restrict__ W1,
                     const float* __restrict__ W2, const float* __restrict__ W3,
                     __nv_bfloat16* __restrict__ hi, __nv_bfloat16* __restrict__ lo)
{
    __shared__ float t[32][33];
    int z = blockIdx.z;
    const float* src = (z == 0) ? W0 : (z == 1) ? W1 : (z == 2) ? W2 : W3;
    int k = blockIdx.y * 32 + threadIdx.y;
    int n = blockIdx.x * 32 + threadIdx.x;
    t[threadIdx.y][threadIdx.x] = src[k * MD + n];
    __syncthreads();
    int nn = blockIdx.x * 32 + threadIdx.y;
    int kk = blockIdx.y * 32 + threadIdx.x;
    float v = t[threadIdx.x][threadIdx.y];
    __nv_bfloat16 h = __float2bfloat16(v);
    __nv_bfloat16 l = __float2bfloat16(v - __bfloat162float(h));
    size_t o = (size_t)z * MD * MD + (size_t)nn * MD + kk;
    hi[o] = h;
    lo[o] = l;
}

// ======================= mma.sync GEMM (unchanged, known-good) ================
#define GBK 32
#define NCHK (MD / GBK)
#define SROW 40
#define BUF_E (128 * SROW)
#define SMEM_TOTAL (8 * BUF_E * 2)

__global__ __launch_bounds__(256, 1)
void gemm_mma(const __nv_bfloat16* __restrict__ Ahi, const __nv_bfloat16* __restrict__ Alo,
              const __nv_bfloat16* __restrict__ Bthi, const __nv_bfloat16* __restrict__ Btlo,
              const float* __restrict__ b0, const float* __restrict__ b1,
              const float* __restrict__ b2,
              float* __restrict__ Cf,
              __nv_bfloat16* __restrict__ H0, __nv_bfloat16* __restrict__ H1,
              __nv_bfloat16* __restrict__ H2,
              __nv_bfloat16* __restrict__ L0, __nv_bfloat16* __restrict__ L1,
              __nv_bfloat16* __restrict__ L2)
{
    extern __shared__ __nv_bfloat16 smem[];
    const int tid  = threadIdx.x;
    const int wid  = tid >> 5;
    const int lane = tid & 31;
    const int wm   = wid & 3;
    const int wn   = wid >> 2;

    const int z = blockIdx.z;
    const float* bias = (z == 0) ? b0 : (z == 1) ? b1 : b2;
    __nv_bfloat16* Hout = (z == 0) ? H0 : (z == 1) ? H1 : H2;
    __nv_bfloat16* Lout = (z == 0) ? L0 : (z == 1) ? L1 : L2;
    const __nv_bfloat16* Bh = Bthi + (size_t)z * MD * MD;
    const __nv_bfloat16* Bl = Btlo + (size_t)z * MD * MD;

    const int n0 = blockIdx.x * 128;
    const int m0 = blockIdx.y * 128;

    __nv_bfloat16* sAh = smem;
    __nv_bfloat16* sAl = smem + 2 * BUF_E;
    __nv_bfloat16* sBh = smem + 4 * BUF_E;
    __nv_bfloat16* sBl = smem + 6 * BUF_E;

    int r0g = (tid + 0)   >> 2, c0g = ((tid + 0)   & 3) << 3;
    int r1g = (tid + 256) >> 2, c1g = ((tid + 256) & 3) << 3;
    const size_t gA0 = (size_t)(m0 + r0g) * MD + c0g;
    const size_t gA1 = (size_t)(m0 + r1g) * MD + c1g;
    const size_t gB0 = (size_t)(n0 + r0g) * MD + c0g;
    const size_t gB1 = (size_t)(n0 + r1g) * MD + c1g;
    const int s0 = r0g * SROW + c0g;
    const int s1 = r1g * SROW + c1g;

    const uint32_t base_u32 = smem_to_u32(smem);
    const int a_r = wm * 32 + (lane & 15);
    const int a_c = (lane >> 4) << 3;
    const int b_r = wn * 64 + ((lane >> 4) << 3) + (lane & 7);
    const int b_c = ((lane >> 3) & 1) << 3;

    float acc[2][8][4];
    #pragma unroll
    for (int i = 0; i < 2; i++)
        #pragma unroll
        for (int j = 0; j < 8; j++)
            #pragma unroll
            for (int q = 0; q < 4; q++) acc[i][j][q] = 0.f;

    {
        *(uint4*)(sAh + s0) = *(const uint4*)(Ahi + gA0);
        *(uint4*)(sAh + s1) = *(const uint4*)(Ahi + gA1);
        *(uint4*)(sAl + s0) = *(const uint4*)(Alo + gA0);
        *(uint4*)(sAl + s1) = *(const uint4*)(Alo + gA1);
        *(uint4*)(sBh + s0) = *(const uint4*)(Bh + gB0);
        *(uint4*)(sBh + s1) = *(const uint4*)(Bh + gB1);
        *(uint4*)(sBl + s0) = *(const uint4*)(Bl + gB0);
        *(uint4*)(sBl + s1) = *(const uint4*)(Bl + gB1);
    }
    __syncthreads();

    for (int ch = 0; ch < NCHK; ch++) {
        const int cur = ch & 1;
        const int nxt = cur ^ 1;

        uint4 pA0h, pA1h, pA0l, pA1l, pB0h, pB1h, pB0l, pB1l;
        if (ch < NCHK - 1) {
            const int kc = (ch + 1) * GBK;
            pA0h = *(const uint4*)(Ahi + gA0 + kc);
            pA1h = *(const uint4*)(Ahi + gA1 + kc);
            pA0l = *(const uint4*)(Alo + gA0 + kc);
            pA1l = *(const uint4*)(Alo + gA1 + kc);
            pB0h = *(const uint4*)(Bh + gB0 + kc);
            pB1h = *(const uint4*)(Bh + gB1 + kc);
            pB0l = *(const uint4*)(Bl + gB0 + kc);
            pB1l = *(const uint4*)(Bl + gB1 + kc);
        }

        const uint32_t stA = base_u32 + (uint32_t)(cur * BUF_E) * 2;
        #pragma unroll
        for (int ks = 0; ks < 2; ks++) {
            uint32_t ah[2][4], al[2][4], bh[4][4], bl[4][4];
            const int kcol = ks * 16;
            #pragma unroll
            for (int mf = 0; mf < 2; mf++) {
                uint32_t off = (uint32_t)((a_r + mf * 16) * SROW + a_c + kcol) * 2;
                ldsm_x4(ah[mf], stA + 0 * (2 * BUF_E * 2) + off);
                ldsm_x4(al[mf], stA + 1 * (2 * BUF_E * 2) + off);
            }
            #pragma unroll
            for (int nf2 = 0; nf2 < 4; nf2++) {
                uint32_t off = (uint32_t)((b_r + nf2 * 16) * SROW + b_c + kcol) * 2;
                ldsm_x4(bh[nf2], stA + 2 * (2 * BUF_E * 2) + off);
                ldsm_x4(bl[nf2], stA + 3 * (2 * BUF_E * 2) + off);
            }
            #pragma unroll
            for (int mf = 0; mf < 2; mf++)
                #pragma unroll
                for (int nf = 0; nf < 8; nf++) {
                    const uint32_t* bhp = &bh[nf >> 1][(nf & 1) * 2];
                    const uint32_t* blp = &bl[nf >> 1][(nf & 1) * 2];
                    mma_bf16(acc[mf][nf], ah[mf], bhp);
                    mma_bf16(acc[mf][nf], ah[mf], blp);
                    mma_bf16(acc[mf][nf], al[mf], bhp);
                }
        }

        if (ch < NCHK - 1) {
            __nv_bfloat16* dAh = sAh + nxt * BUF_E;
            __nv_bfloat16* dAl = sAl + nxt * BUF_E;
            __nv_bfloat16* dBh = sBh + nxt * BUF_E;
            __nv_bfloat16* dBl = sBl + nxt * BUF_E;
            *(uint4*)(dAh + s0) = pA0h;  *(uint4*)(dAh + s1) = pA1h;
            *(uint4*)(dAl + s0) = pA0l;  *(uint4*)(dAl + s1) = pA1l;
            *(uint4*)(dBh + s0) = pB0h;  *(uint4*)(dBh + s1) = pB1h;
            *(uint4*)(dBl + s0) = pB0l;  *(uint4*)(dBl + s1) = pB1l;
        }
        __syncthreads();
    }

    const int tq = lane >> 2;
    const int tr = lane & 3;
    #pragma unroll
    for (int mf = 0; mf < 2; mf++) {
        #pragma unroll
        for (int nf = 0; nf < 8; nf++) {
            const int n = n0 + wn * 64 + nf * 8 + tr * 2;
            const float bv0 = bias[n], bv1 = bias[n + 1];
            const int m_top = m0 + wm * 32 + mf * 16 + tq;
            float v0 = acc[mf][nf][0] + bv0, v1 = acc[mf][nf][1] + bv1;
            float v2 = acc[mf][nf][2] + bv0, v3 = acc[mf][nf][3] + bv1;
            if (Hout) {
                uint32_t h01, l01, h23, l23;
                split2(v0, v1, h01, l01);
                split2(v2, v3, h23, l23);
                *(uint32_t*)(Hout + (size_t)m_top * MD + n)       = h01;
                *(uint32_t*)(Lout + (size_t)m_top * MD + n)       = l01;
                *(uint32_t*)(Hout + (size_t)(m_top + 8) * MD + n) = h23;
                *(uint32_t*)(Lout + (size_t)(m_top + 8) * MD + n) = l23;
            } else {
                float2 w0, w1;
                w0.x = v0; w0.y = v1;
                w1.x = v2; w1.y = v3;
                *(float2*)(Cf + (size_t)m_top * MD + n)       = w0;
                *(float2*)(Cf + (size_t)(m_top + 8) * MD + n) = w1;
            }
        }
    }
}

// ======================= flash attention v2: cp.async pipelined ===============
// CTA: 128 q-rows x one (b,h). 8 warps x 16 q-rows. kv tiles of 64,
// double-buffered K/V via cp.async, V loaded straight + ldmatrix.trans.
#define SR2 72                    // 64 + 8 pad (elems); row = 144B (16B aligned)
#define KBUF (64 * SR2)           // elems per 64x72 buffer
#define ATT_SMEM (8 * KBUF * 2)   // 2 stages x 4 buffers, bytes

__global__ __launch_bounds__(256, 1)
void attn_mma(const float* __restrict__ mask,
              __nv_bfloat16* __restrict__ chi, __nv_bfloat16* __restrict__ clo)
{
    extern __shared__ __nv_bfloat16 sm[];    // [stage][Kh|Kl|Vh|Vl][64][SR2]
    __shared__ float ms[2][64];

    const int tid  = threadIdx.x;
    const int wid  = tid >> 5;
    const int lane = tid & 31;
    const int bh   = blockIdx.y;
    const int b    = bh >> 4;
    const int h    = bh & 15;
    const int q0   = blockIdx.x * 128;

    const uint32_t sbase = smem_to_u32(sm);

    // ---- load Q tile (128x64 hi/lo) into stage area, frag it ----
    #pragma unroll
    for (int it = 0; it < 4; it++) {
        int i = tid + it * 256;
        int r = i >> 3, c = (i & 7) << 3;
        size_t g = (size_t)(b * MS + q0 + r) * MD + h * 64 + c;
        *(uint4*)&sm[r * SR2 + c]            = *(const uint4*)(g_qhi + g);
        *(uint4*)&sm[2 * KBUF + r * SR2 + c] = *(const uint4*)(g_qlo + g);
    }
    __syncthreads();

    uint32_t qh[4][4], ql[4][4];
    {
        const int a_r = wid * 16 + (lane & 15);
        const int a_c = (lane >> 4) << 3;
        #pragma unroll
        for (int kf = 0; kf < 4; kf++) {
            uint32_t off = (uint32_t)(a_r * SR2 + a_c + kf * 16) * 2;
            ldsm_x4(qh[kf], sbase + off);
            ldsm_x4(ql[kf], sbase + 2 * KBUF * 2 + off);
        }
    }
    __syncthreads();    // all warps done reading Q before buffers are reused

    // per-thread cp.async source/dest geometry (2 chunks per buffer)
    const int cr0 = (tid + 0)   >> 3, cc0 = ((tid + 0)   & 7) << 3;
    const int cr1 = (tid + 256) >> 3, cc1 = ((tid + 256) & 7) << 3;
    const uint32_t d0 = (uint32_t)(cr0 * SR2 + cc0) * 2;
    const uint32_t d1 = (uint32_t)(cr1 * SR2 + cc1) * 2;
    const uint32_t msb = smem_to_u32(ms);

    // fragment addressing
    const int b_r = ((lane >> 4) << 3) + (lane & 7);      // K (non-trans)
    const int b_c = ((lane >> 3) & 1) << 3;
    const int v_r = (((lane >> 3) & 1) << 3) + (lane & 7); // V (trans)
    const int v_c = (lane >> 4) << 3;
    const int cq  = (lane & 3) * 2;

    float m0 = -INFINITY, m1 = -INFINITY, l0 = 0.f, l1 = 0.f;
    float o[8][4];
    #pragma unroll
    for (int nf = 0; nf < 8; nf++)
        #pragma unroll
        for (int q = 0; q < 4; q++) o[nf][q] = 0.f;

    // ---- prologue: issue stage 0 loads ----
    {
        size_t g0 = (size_t)(b * MS + cr0) * MD + h * 64 + cc0;
        size_t g1 = (size_t)(b * MS + cr1) * MD + h * 64 + cc1;
        CP_ASYNC16(sbase + 0 * KBUF * 2 + d0, g_khi + g0);
        CP_ASYNC16(sbase + 0 * KBUF * 2 + d1, g_khi + g1);
        CP_ASYNC16(sbase + 1 * KBUF * 2 + d0, g_klo + g0);
        CP_ASYNC16(sbase + 1 * KBUF * 2 + d1, g_klo + g1);
        CP_ASYNC16(sbase + 2 * KBUF * 2 + d0, g_vhi + g0);
        CP_ASYNC16(sbase + 2 * KBUF * 2 + d1, g_vhi + g1);
        CP_ASYNC16(sbase + 3 * KBUF * 2 + d0, g_vlo + g0);
        CP_ASYNC16(sbase + 3 * KBUF * 2 + d1, g_vlo + g1);
        if (tid < 16)
            CP_ASYNC16(msb + tid * 16, mask + b * MS + tid * 4);
        CP_COMMIT();
    }

    for (int kt = 0; kt < MS / 64; kt++) {
        const int cur = kt & 1;
        CP_WAIT0();
        __syncthreads();

        // issue next tile into other stage (overlaps with compute below)
        if (kt < MS / 64 - 1) {
            const uint32_t stN = sbase + (uint32_t)((cur ^ 1) * 4 * KBUF) * 2;
            size_t g0 = (size_t)(b * MS + (kt + 1) * 64 + cr0) * MD + h * 64 + cc0;
            size_t g1 = (size_t)(b * MS + (kt + 1) * 64 + cr1) * MD + h * 64 + cc1;
            CP_ASYNC16(stN + 0 * KBUF * 2 + d0, g_khi + g0);
            CP_ASYNC16(stN + 0 * KBUF * 2 + d1, g_khi + g1);
            CP_ASYNC16(stN + 1 * KBUF * 2 + d0, g_klo + g0);
            CP_ASYNC16(stN + 1 * KBUF * 2 + d1, g_klo + g1);
            CP_ASYNC16(stN + 2 * KBUF * 2 + d0, g_vhi + g0);
            CP_ASYNC16(stN + 2 * KBUF * 2 + d1, g_vhi + g1);
            CP_ASYNC16(stN + 3 * KBUF * 2 + d0, g_vlo + g0);
            CP_ASYNC16(stN + 3 * KBUF * 2 + d1, g_vlo + g1);
            if (tid < 16)
                CP_ASYNC16(msb + (cur ^ 1) * 256 + tid * 16,
                           mask + b * MS + (kt + 1) * 64 + tid * 4);
            CP_COMMIT();
        }

        const uint32_t stC = sbase + (uint32_t)(cur * 4 * KBUF) * 2;

        // ---- S = Q K^T (3-term) ----
        float s[8][4];
        #pragma unroll
        for (int nf = 0; nf < 8; nf++)
            #pragma unroll
            for (int q = 0; q < 4; q++) s[nf][q] = 0.f;

        #pragma unroll
        for (int ks = 0; ks < 4; ks++) {
            uint32_t kh[4][4], kl[4][4];
            #pragma unroll
            for (int nf2 = 0; nf2 < 4; nf2++) {
                uint32_t off = (uint32_t)((b_r + nf2 * 16) * SR2 + b_c + ks * 16) * 2;
                ldsm_x4(kh[nf2], stC + 0 * KBUF * 2 + off);
                ldsm_x4(kl[nf2], stC + 1 * KBUF * 2 + off);
            }
            #pragma unroll
            for (int nf = 0; nf < 8; nf++) {
                const uint32_t* bhp = &kh[nf >> 1][(nf & 1) * 2];
                const uint32_t* blp = &kl[nf >> 1][(nf & 1) * 2];
                mma_bf16(s[nf], qh[ks], bhp);
                mma_bf16(s[nf], qh[ks], blp);
                mma_bf16(s[nf], ql[ks], bhp);
            }
        }

        // ---- scale + mask ----
        #pragma unroll
        for (int nf = 0; nf < 8; nf++) {
            float ma = ms[cur][nf * 8 + cq], mb = ms[cur][nf * 8 + cq + 1];
            s[nf][0] = s[nf][0] * 0.125f + ma;
            s[nf][1] = s[nf][1] * 0.125f + mb;
            s[nf][2] = s[nf][2] * 0.125f + ma;
            s[nf][3] = s[nf][3] * 0.125f + mb;
        }

        // ---- online softmax ----
        float rm0 = -INFINITY, rm1 = -INFINITY;
        #pragma unroll
        for (int nf = 0; nf < 8; nf++) {
            rm0 = fmaxf(rm0, fmaxf(s[nf][0], s[nf][1]));
            rm1 = fmaxf(rm1, fmaxf(s[nf][2], s[nf][3]));
        }
        rm0 = fmaxf(rm0, __shfl_xor_sync(0xffffffffu, rm0, 1));
        rm0 = fmaxf(rm0, __shfl_xor_sync(0xffffffffu, rm0, 2));
        rm1 = fmaxf(rm1, __shfl_xor_sync(0xffffffffu, rm1, 1));
        rm1 = fmaxf(rm1, __shfl_xor_sync(0xffffffffu, rm1, 2));
        float nm0 = fmaxf(m0, rm0), nm1 = fmaxf(m1, rm1);
        float al0 = __expf(m0 - nm0), al1 = __expf(m1 - nm1);
        m0 = nm0;  m1 = nm1;

        float ls0 = 0.f, ls1 = 0.f;
        #pragma unroll
        for (int nf = 0; nf < 8; nf++) {
            s[nf][0] = __expf(s[nf][0] - nm0);
            s[nf][1] = __expf(s[nf][1] - nm0);
            s[nf][2] = __expf(s[nf][2] - nm1);
            s[nf][3] = __expf(s[nf][3] - nm1);
            ls0 += s[nf][0] + s[nf][1];
            ls1 += s[nf][2] + s[nf][3];
        }
        ls0 += __shfl_xor_sync(0xffffffffu, ls0, 1);
        ls0 += __shfl_xor_sync(0xffffffffu, ls0, 2);
        ls1 += __shfl_xor_sync(0xffffffffu, ls1, 1);
        ls1 += __shfl_xor_sync(0xffffffffu, ls1, 2);
        l0 = l0 * al0 + ls0;
        l1 = l1 * al1 + ls1;

        #pragma unroll
        for (int nf = 0; nf < 8; nf++) {
            o[nf][0] *= al0;  o[nf][1] *= al0;
            o[nf][2] *= al1;  o[nf][3] *= al1;
        }

        // ---- repack P -> A-fragments, hi/lo ----
        uint32_t ph[4][4], pl[4][4];
        #pragma unroll
        for (int kf = 0; kf < 4; kf++) {
            split2(s[2*kf][0],   s[2*kf][1],   ph[kf][0], pl[kf][0]);
            split2(s[2*kf][2],   s[2*kf][3],   ph[kf][1], pl[kf][1]);
            split2(s[2*kf+1][0], s[2*kf+1][1], ph[kf][2], pl[kf][2]);
            split2(s[2*kf+1][2], s[2*kf+1][3], ph[kf][3], pl[kf][3]);
        }

        // ---- O += P V (3-term), V straight + ldmatrix.trans ----
        #pragma unroll
        for (int ks = 0; ks < 4; ks++) {
            uint32_t vh[4][4], vl[4][4];
            #pragma unroll
            for (int nf2 = 0; nf2 < 4; nf2++) {
                uint32_t off = (uint32_t)((ks * 16 + v_r) * SR2 + nf2 * 16 + v_c) * 2;
                ldsm_x4_t(vh[nf2], stC + 2 * KBUF * 2 + off);
                ldsm_x4_t(vl[nf2], stC + 3 * KBUF * 2 + off);
            }
            #pragma unroll
            for (int nf = 0; nf < 8; nf++) {
                const uint32_t* bhp = &vh[nf >> 1][(nf & 1) * 2];
                const uint32_t* blp = &vl[nf >> 1][(nf & 1) * 2];
                mma_bf16(o[nf], ph[ks], bhp);
                mma_bf16(o[nf], ph[ks], blp);
                mma_bf16(o[nf], pl[ks], bhp);
            }
        }
        __syncthreads();   // all warps done with cur before it is refilled
    }

    // ---- finalize ----
    float i0 = 1.f / l0, i1 = 1.f / l1;
    const int r0 = lane >> 2;
    const size_t mrow = (size_t)(b * MS + q0 + wid * 16 + r0);
    #pragma unroll
    for (int nf = 0; nf < 8; nf++) {
        int d = h * 64 + nf * 8 + cq;
        float v0 = o[nf][0] * i0, v1 = o[nf][1] * i0;
        float v2 = o[nf][2] * i1, v3 = o[nf][3] * i1;
        uint32_t h01, l01, h23, l23;
        split2(v0, v1, h01, l01);
        split2(v2, v3, h23, l23);
        *(uint32_t*)(chi + mrow * MD + d)       = h01;
        *(uint32_t*)(clo + mrow * MD + d)       = l01;
        *(uint32_t*)(chi + (mrow + 8) * MD + d) = h23;
        *(uint32_t*)(clo + (mrow + 8) * MD + d) = l23;
    }
}

// ---------------- launch ----------------
extern "C" void kernel_launch(void* const* d_in, const int* in_sizes, int n_in,
                              void* d_out, int out_size)
{
    const float* x    = (const float*)d_in[0];
    const float* mask = (const float*)d_in[1];
    const float* Wq   = (const float*)d_in[2];
    const float* bq   = (const float*)d_in[3];
    const float* Wk   = (const float*)d_in[4];
    const float* bk   = (const float*)d_in[5];
    const float* Wv   = (const float*)d_in[6];
    const float* bv   = (const float*)d_in[7];
    const float* Wo   = (const float*)d_in[8];
    const float* bo   = (const float*)d_in[9];
    float* out = (float*)d_out;

    __nv_bfloat16 *pxhi, *pxlo, *pqhi, *pqlo, *pkhi, *pklo, *pvhi, *pvlo;
    __nv_bfloat16 *pchi, *pclo, *pwthi, *pwtlo;
    cudaGetSymbolAddress((void**)&pxhi,  g_xhi);
    cudaGetSymbolAddress((void**)&pxlo,  g_xlo);
    cudaGetSymbolAddress((void**)&pqhi,  g_qhi);
    cudaGetSymbolAddress((void**)&pqlo,  g_qlo);
    cudaGetSymbolAddress((void**)&pkhi,  g_khi);
    cudaGetSymbolAddress((void**)&pklo,  g_klo);
    cudaGetSymbolAddress((void**)&pvhi,  g_vhi);
    cudaGetSymbolAddress((void**)&pvlo,  g_vlo);
    cudaGetSymbolAddress((void**)&pchi,  g_chi);
    cudaGetSymbolAddress((void**)&pclo,  g_clo);
    cudaGetSymbolAddress((void**)&pwthi, g_wthi);
    cudaGetSymbolAddress((void**)&pwtlo, g_wtlo);

    cudaFuncSetAttribute(gemm_mma, cudaFuncAttributeMaxDynamicSharedMemorySize, SMEM_TOTAL);
    cudaFuncSetAttribute(attn_mma, cudaFuncAttributeMaxDynamicSharedMemorySize, ATT_SMEM);

    // 0) prep
    split_convert<<<(MM * MD / 4) / 256, 256>>>(x, pxhi, pxlo);
    dim3 gt(MD / 32, MD / 32, 4);
    transpose_split<<<gt, dim3(32, 32)>>>(Wq, Wk, Wv, Wo, pwthi, pwtlo);

    // 1) fused QKV projections -> bf16 hi/lo outputs
    dim3 gqkv(MD / 128, MM / 128, 3);
    gemm_mma<<<gqkv, 256, SMEM_TOTAL>>>(pxhi, pxlo, pwthi, pwtlo,
                                        bq, bk, bv, nullptr,
                                        pqhi, pkhi, pvhi, pqlo, pklo, pvlo);

    // 2) flash attention (tensor cores, pipelined) -> ctx hi/lo
    dim3 gattn(MS / 128, MB * MNH);
    attn_mma<<<gattn, 256, ATT_SMEM>>>(mask, pchi, pclo);

    // 3) O projection -> fp32 out
    dim3 go(MD / 128, MM / 128, 1);
    gemm_mma<<<go, 256, SMEM_TOTAL>>>(pchi, pclo, pwthi + 3 * (size_t)MD * MD,
                                      pwtlo + 3 * (size_t)MD * MD,
                                      bo, bo, bo, out,
                                      nullptr, nullptr, nullptr,
                                      nullptr, nullptr, nullptr);
}